// round 1
// baseline (speedup 1.0000x reference)
#include <cuda_runtime.h>
#include <cuda_bf16.h>
#include <cstdint>

// Problem dims (fixed by the reference)
static constexpr int BATCH = 16;
static constexpr int LQ    = 2048;
static constexpr int LK    = 2048;
static constexpr int DIM   = 128;

static constexpr float SCALE = 0.08838834764831845f; // 1/sqrt(128)

// ---------------------------------------------------------------------------
// Kernel 1: S[b,q,k] = scale * sum_d Q[b,q,d] * K[b,k,d]
// 128x128 tile per block, BK=16, 256 threads, 8x8 per thread.
// Both operands are row-major with contraction dim (d) contiguous -> NT GEMM.
// ---------------------------------------------------------------------------
__global__ __launch_bounds__(256) void qk_kernel(const float* __restrict__ Q,
                                                 const float* __restrict__ Km,
                                                 float* __restrict__ S) {
    constexpr int BM = 128, BN = 128, BK = 16;
    __shared__ float As[BK][BM];   // As[d][q]
    __shared__ float Bs[BK][BN];   // Bs[d][k]

    const int b  = blockIdx.z;
    const int qt = blockIdx.y * BM;
    const int kt = blockIdx.x * BN;

    const float* Qb = Q  + (size_t)b * LQ * DIM + (size_t)qt * DIM;
    const float* Kb = Km + (size_t)b * LK * DIM + (size_t)kt * DIM;
    float*       Sb = S  + (size_t)b * LQ * LK;

    const int tid = threadIdx.x;
    const int tx  = tid & 15;       // 0..15
    const int ty  = tid >> 4;       // 0..15

    float acc[8][8];
#pragma unroll
    for (int i = 0; i < 8; i++)
#pragma unroll
        for (int j = 0; j < 8; j++) acc[i][j] = 0.f;

    for (int d0 = 0; d0 < DIM; d0 += BK) {
        // Load 128x16 tiles of Q and K (512 float4 each), transpose into smem.
#pragma unroll
        for (int p = 0; p < 2; p++) {
            int f   = tid + p * 256;   // 0..511
            int row = f >> 2;
            int c4  = (f & 3) * 4;
            float4 va = *reinterpret_cast<const float4*>(Qb + (size_t)row * DIM + d0 + c4);
            As[c4 + 0][row] = va.x;
            As[c4 + 1][row] = va.y;
            As[c4 + 2][row] = va.z;
            As[c4 + 3][row] = va.w;
            float4 vb = *reinterpret_cast<const float4*>(Kb + (size_t)row * DIM + d0 + c4);
            Bs[c4 + 0][row] = vb.x;
            Bs[c4 + 1][row] = vb.y;
            Bs[c4 + 2][row] = vb.z;
            Bs[c4 + 3][row] = vb.w;
        }
        __syncthreads();

#pragma unroll
        for (int kk = 0; kk < BK; kk++) {
            float a[8], bb[8];
            *reinterpret_cast<float4*>(&a[0])  = *reinterpret_cast<const float4*>(&As[kk][ty * 8]);
            *reinterpret_cast<float4*>(&a[4])  = *reinterpret_cast<const float4*>(&As[kk][ty * 8 + 4]);
            *reinterpret_cast<float4*>(&bb[0]) = *reinterpret_cast<const float4*>(&Bs[kk][tx * 8]);
            *reinterpret_cast<float4*>(&bb[4]) = *reinterpret_cast<const float4*>(&Bs[kk][tx * 8 + 4]);
#pragma unroll
            for (int i = 0; i < 8; i++)
#pragma unroll
                for (int j = 0; j < 8; j++) acc[i][j] = fmaf(a[i], bb[j], acc[i][j]);
        }
        __syncthreads();
    }

    // Epilogue: scale and store
#pragma unroll
    for (int i = 0; i < 8; i++) {
        const int gq = qt + ty * 8 + i;
        float* dst = Sb + (size_t)gq * LK + kt + tx * 8;
        float4 o0, o1;
        o0.x = acc[i][0] * SCALE; o0.y = acc[i][1] * SCALE;
        o0.z = acc[i][2] * SCALE; o0.w = acc[i][3] * SCALE;
        o1.x = acc[i][4] * SCALE; o1.y = acc[i][5] * SCALE;
        o1.z = acc[i][6] * SCALE; o1.w = acc[i][7] * SCALE;
        *reinterpret_cast<float4*>(dst)     = o0;
        *reinterpret_cast<float4*>(dst + 4) = o1;
    }
}

// ---------------------------------------------------------------------------
// Kernel 2: in-place row softmax over the last axis (LK = 2048).
// One block (256 threads) per row; 8 values/thread kept in registers.
// ---------------------------------------------------------------------------
__device__ __forceinline__ float blockReduceMax(float v, float* red) {
#pragma unroll
    for (int o = 16; o > 0; o >>= 1) v = fmaxf(v, __shfl_xor_sync(0xFFFFFFFFu, v, o));
    const int lane = threadIdx.x & 31, wid = threadIdx.x >> 5;
    if (lane == 0) red[wid] = v;
    __syncthreads();
    if (wid == 0) {
        v = (lane < 8) ? red[lane] : -INFINITY;
#pragma unroll
        for (int o = 4; o > 0; o >>= 1) v = fmaxf(v, __shfl_xor_sync(0xFFFFFFFFu, v, o));
        if (lane == 0) red[0] = v;
    }
    __syncthreads();
    return red[0];
}

__device__ __forceinline__ float blockReduceSum(float v, float* red) {
#pragma unroll
    for (int o = 16; o > 0; o >>= 1) v += __shfl_xor_sync(0xFFFFFFFFu, v, o);
    const int lane = threadIdx.x & 31, wid = threadIdx.x >> 5;
    if (lane == 0) red[wid] = v;
    __syncthreads();
    if (wid == 0) {
        v = (lane < 8) ? red[lane] : 0.f;
#pragma unroll
        for (int o = 4; o > 0; o >>= 1) v += __shfl_xor_sync(0xFFFFFFFFu, v, o);
        if (lane == 0) red[0] = v;
    }
    __syncthreads();
    return red[0];
}

__global__ __launch_bounds__(256) void softmax_kernel(float* __restrict__ S) {
    __shared__ float red[8 + 24]; // reduce scratch (first 8 used)
    float* p = S + (size_t)blockIdx.x * LK + threadIdx.x * 8;

    float v[8];
    float4 v0 = *reinterpret_cast<const float4*>(p);
    float4 v1 = *reinterpret_cast<const float4*>(p + 4);
    v[0] = v0.x; v[1] = v0.y; v[2] = v0.z; v[3] = v0.w;
    v[4] = v1.x; v[5] = v1.y; v[6] = v1.z; v[7] = v1.w;

    float m = v[0];
#pragma unroll
    for (int i = 1; i < 8; i++) m = fmaxf(m, v[i]);
    m = blockReduceMax(m, red);

    float e[8], s = 0.f;
#pragma unroll
    for (int i = 0; i < 8; i++) { e[i] = expf(v[i] - m); s += e[i]; }
    __syncthreads(); // protect red[] reuse
    s = blockReduceSum(s, red);
    const float inv = 1.f / s;

    float4 o0, o1;
    o0.x = e[0] * inv; o0.y = e[1] * inv; o0.z = e[2] * inv; o0.w = e[3] * inv;
    o1.x = e[4] * inv; o1.y = e[5] * inv; o1.z = e[6] * inv; o1.w = e[7] * inv;
    *reinterpret_cast<float4*>(p)     = o0;
    *reinterpret_cast<float4*>(p + 4) = o1;
}

// ---------------------------------------------------------------------------
// Kernel 3: R[b,q,d] = sum_k P[b,q,k] * V[b,k,d]   (NN GEMM, BN = full D = 128)
// ---------------------------------------------------------------------------
__global__ __launch_bounds__(256) void pv_kernel(const float* __restrict__ P,
                                                 const float* __restrict__ V,
                                                 float* __restrict__ R) {
    constexpr int BM = 128, BN = 128, BK = 16;
    __shared__ float As[BK][BM];   // As[k][q] (P^T tile)
    __shared__ float Bs[BK][BN];   // Bs[k][d] (V tile, direct)

    const int b  = blockIdx.z;
    const int qt = blockIdx.y * BM;

    const float* Pb = P + (size_t)b * LQ * LK + (size_t)qt * LK;
    const float* Vb = V + (size_t)b * LK * DIM;
    float*       Rb = R + (size_t)b * LQ * DIM + (size_t)qt * DIM;

    const int tid = threadIdx.x;
    const int tx  = tid & 15;
    const int ty  = tid >> 4;

    float acc[8][8];
#pragma unroll
    for (int i = 0; i < 8; i++)
#pragma unroll
        for (int j = 0; j < 8; j++) acc[i][j] = 0.f;

    for (int k0 = 0; k0 < LK; k0 += BK) {
        // A tile: P[128 rows][16 k], transpose into As
#pragma unroll
        for (int p = 0; p < 2; p++) {
            int f   = tid + p * 256;       // 0..511
            int row = f >> 2;
            int c4  = (f & 3) * 4;
            float4 va = *reinterpret_cast<const float4*>(Pb + (size_t)row * LK + k0 + c4);
            As[c4 + 0][row] = va.x;
            As[c4 + 1][row] = va.y;
            As[c4 + 2][row] = va.z;
            As[c4 + 3][row] = va.w;
            // B tile: V[16 k][128 d] -> direct float4 copy (f covers 512 float4)
            int kk = f >> 5;               // 0..15
            int cc = (f & 31) * 4;         // 0..124
            float4 vb = *reinterpret_cast<const float4*>(Vb + (size_t)(k0 + kk) * DIM + cc);
            *reinterpret_cast<float4*>(&Bs[kk][cc]) = vb;
        }
        __syncthreads();

#pragma unroll
        for (int kk = 0; kk < BK; kk++) {
            float a[8], bb[8];
            *reinterpret_cast<float4*>(&a[0])  = *reinterpret_cast<const float4*>(&As[kk][ty * 8]);
            *reinterpret_cast<float4*>(&a[4])  = *reinterpret_cast<const float4*>(&As[kk][ty * 8 + 4]);
            *reinterpret_cast<float4*>(&bb[0]) = *reinterpret_cast<const float4*>(&Bs[kk][tx * 8]);
            *reinterpret_cast<float4*>(&bb[4]) = *reinterpret_cast<const float4*>(&Bs[kk][tx * 8 + 4]);
#pragma unroll
            for (int i = 0; i < 8; i++)
#pragma unroll
                for (int j = 0; j < 8; j++) acc[i][j] = fmaf(a[i], bb[j], acc[i][j]);
        }
        __syncthreads();
    }

#pragma unroll
    for (int i = 0; i < 8; i++) {
        float* dst = Rb + (size_t)(ty * 8 + i) * DIM + tx * 8;
        float4 o0, o1;
        o0.x = acc[i][0]; o0.y = acc[i][1]; o0.z = acc[i][2]; o0.w = acc[i][3];
        o1.x = acc[i][4]; o1.y = acc[i][5]; o1.z = acc[i][6]; o1.w = acc[i][7];
        *reinterpret_cast<float4*>(dst)     = o0;
        *reinterpret_cast<float4*>(dst + 4) = o1;
    }
}

// ---------------------------------------------------------------------------
// Launch: d_out = [ R (B*LQ*D floats) | P (B*LQ*LK floats) ]
// ---------------------------------------------------------------------------
extern "C" void kernel_launch(void* const* d_in, const int* in_sizes, int n_in,
                              void* d_out, int out_size) {
    const float* Q = (const float*)d_in[0];
    const float* K = (const float*)d_in[1];
    const float* V = (const float*)d_in[2];

    float* R = (float*)d_out;
    float* P = (float*)d_out + (size_t)BATCH * LQ * DIM;

    // 1) scores into P region
    {
        dim3 grid(LK / 128, LQ / 128, BATCH);
        qk_kernel<<<grid, 256>>>(Q, K, P);
    }
    // 2) in-place row softmax
    {
        dim3 grid(BATCH * LQ);
        softmax_kernel<<<grid, 256>>>(P);
    }
    // 3) R = P @ V
    {
        dim3 grid(1, LQ / 128, BATCH);
        pv_kernel<<<grid, 256>>>(P, V, R);
    }
}

// round 3
// speedup vs baseline: 1.4520x; 1.4520x over previous
#include <cuda_runtime.h>
#include <cuda_bf16.h>
#include <cstdint>

// ---------------------------------------------------------------------------
// Problem dims
// ---------------------------------------------------------------------------
static constexpr int BATCH = 16;
static constexpr int LQ    = 2048;
static constexpr int LK    = 2048;
static constexpr int DIM   = 128;
static constexpr float SCALE = 0.08838834764831845f; // 1/sqrt(128)

static constexpr int NPS = LK / 32;   // 64 partial sums per row (one per 32-col slice)

// Deterministic per-(row, 32-col-slice) partial sums of exp(scores)
__device__ float g_psums[(size_t)BATCH * LQ * NPS];

// ---------------------------------------------------------------------------
// SMEM layout: 4 bf16 tiles of 128x128, row stride 136 halves (272B, padded)
// ---------------------------------------------------------------------------
static constexpr int RS     = 136;            // halves per row
static constexpr int RSB    = RS * 2;         // 272 bytes per row
static constexpr int TILE_B = 128 * RSB;      // 34816 bytes per tile
static constexpr int SM_QK  = 4 * TILE_B;           // Qhi,Qlo,Khi,Klo
static constexpr int SM_PV  = 4 * TILE_B + 512;     // + inv[128]

// ---------------------------------------------------------------------------
// PTX helpers (all plain sm_80-class: ldmatrix + mma.sync — no 'a' features)
// ---------------------------------------------------------------------------
__device__ __forceinline__ uint32_t smem_u32(const void* p) {
    uint32_t a;
    asm("{ .reg .u64 t; cvta.to.shared.u64 t, %1; cvt.u32.u64 %0, t; }" : "=r"(a) : "l"(p));
    return a;
}

__device__ __forceinline__ void ldsm4(uint32_t (&r)[4], uint32_t addr) {
    asm volatile("ldmatrix.sync.aligned.m8n8.x4.shared.b16 {%0,%1,%2,%3}, [%4];"
                 : "=r"(r[0]), "=r"(r[1]), "=r"(r[2]), "=r"(r[3]) : "r"(addr));
}
__device__ __forceinline__ void ldsm4t(uint32_t (&r)[4], uint32_t addr) {
    asm volatile("ldmatrix.sync.aligned.m8n8.x4.trans.shared.b16 {%0,%1,%2,%3}, [%4];"
                 : "=r"(r[0]), "=r"(r[1]), "=r"(r[2]), "=r"(r[3]) : "r"(addr));
}

__device__ __forceinline__ void mma16816(float (&d)[4], const uint32_t (&a)[4],
                                         uint32_t b0, uint32_t b1) {
    asm volatile(
        "mma.sync.aligned.m16n8k16.row.col.f32.bf16.bf16.f32 "
        "{%0,%1,%2,%3},{%4,%5,%6,%7},{%8,%9},{%0,%1,%2,%3};"
        : "+f"(d[0]), "+f"(d[1]), "+f"(d[2]), "+f"(d[3])
        : "r"(a[0]), "r"(a[1]), "r"(a[2]), "r"(a[3]), "r"(b0), "r"(b1));
}

// fp32 -> bf16 hi + bf16 lo (residual) for 4 lanes of a float4
__device__ __forceinline__ void split4(float4 v, uint2& hi, uint2& lo) {
    __nv_bfloat16 h0 = __float2bfloat16_rn(v.x);
    __nv_bfloat16 h1 = __float2bfloat16_rn(v.y);
    __nv_bfloat16 h2 = __float2bfloat16_rn(v.z);
    __nv_bfloat16 h3 = __float2bfloat16_rn(v.w);
    __nv_bfloat16 l0 = __float2bfloat16_rn(v.x - __bfloat162float(h0));
    __nv_bfloat16 l1 = __float2bfloat16_rn(v.y - __bfloat162float(h1));
    __nv_bfloat16 l2 = __float2bfloat16_rn(v.z - __bfloat162float(h2));
    __nv_bfloat16 l3 = __float2bfloat16_rn(v.w - __bfloat162float(h3));
    __nv_bfloat162 a{h0, h1}, b{h2, h3}, c{l0, l1}, d{l2, l3};
    hi.x = *reinterpret_cast<uint32_t*>(&a); hi.y = *reinterpret_cast<uint32_t*>(&b);
    lo.x = *reinterpret_cast<uint32_t*>(&c); lo.y = *reinterpret_cast<uint32_t*>(&d);
}

// ---------------------------------------------------------------------------
// Kernel 1: E[b,q,k] = exp(scale * Q·K^T)  (unnormalized), + row partial sums.
// 128x128 CTA tile, 8 warps (2m x 4n), warp tile 64x32, bf16x3 mma.sync.
// ---------------------------------------------------------------------------
__global__ __launch_bounds__(256, 1) void qk_exp_kernel(const float* __restrict__ Q,
                                                        const float* __restrict__ Km,
                                                        float* __restrict__ E) {
    extern __shared__ char sm[];
    const uint32_t sb = smem_u32(sm);

    const int tid = threadIdx.x, lane = tid & 31, wid = tid >> 5;
    const int wm = wid >> 2, wn = wid & 3;   // warp grid 2 x 4
    const int b = blockIdx.z, qt = blockIdx.y * 128, kt = blockIdx.x * 128;

    const float* Qb = Q  + ((size_t)b * LQ + qt) * DIM;
    const float* Kb = Km + ((size_t)b * LK + kt) * DIM;

    // ---- load fp32, split to bf16 hi/lo in padded smem ----
#pragma unroll
    for (int it = 0; it < 16; ++it) {
        int f = tid + it * 256;            // 0..4095
        int row = f >> 5, col = (f & 31) * 4;
        int so = row * RSB + col * 2;
        uint2 hi, lo;
        split4(*reinterpret_cast<const float4*>(Qb + (size_t)row * DIM + col), hi, lo);
        *reinterpret_cast<uint2*>(sm + 0 * TILE_B + so) = hi;
        *reinterpret_cast<uint2*>(sm + 1 * TILE_B + so) = lo;
        split4(*reinterpret_cast<const float4*>(Kb + (size_t)row * DIM + col), hi, lo);
        *reinterpret_cast<uint2*>(sm + 2 * TILE_B + so) = hi;
        *reinterpret_cast<uint2*>(sm + 3 * TILE_B + so) = lo;
    }
    __syncthreads();

    float acc[4][4][4];
#pragma unroll
    for (int mi = 0; mi < 4; ++mi)
#pragma unroll
        for (int ni = 0; ni < 4; ++ni)
#pragma unroll
            for (int c = 0; c < 4; ++c) acc[mi][ni][c] = 0.f;

    // per-lane ldmatrix address components
    const uint32_t aoff = (uint32_t)((lane & 15) * RSB + (lane >> 4) * 16);
    const uint32_t boff = (uint32_t)(((lane & 7) + (lane >> 4) * 8) * RSB + ((lane >> 3) & 1) * 16);
    const uint32_t aHi = sb + 0 * TILE_B + (uint32_t)(wm * 64) * RSB + aoff;
    const uint32_t aLo = sb + 1 * TILE_B + (uint32_t)(wm * 64) * RSB + aoff;
    const uint32_t bHi = sb + 2 * TILE_B + (uint32_t)(wn * 32) * RSB + boff;
    const uint32_t bLo = sb + 3 * TILE_B + (uint32_t)(wn * 32) * RSB + boff;

#pragma unroll
    for (int pass = 0; pass < 3; ++pass) {
        const uint32_t ab = (pass == 2) ? aLo : aHi;
        const uint32_t bb = (pass == 1) ? bLo : bHi;
#pragma unroll
        for (int ks = 0; ks < 8; ++ks) {
            uint32_t a[4][4];
#pragma unroll
            for (int mi = 0; mi < 4; ++mi) ldsm4(a[mi], ab + (uint32_t)(mi * 16) * RSB + ks * 32);
            uint32_t bf[2][4];
#pragma unroll
            for (int np = 0; np < 2; ++np) ldsm4(bf[np], bb + (uint32_t)(np * 16) * RSB + ks * 32);
#pragma unroll
            for (int mi = 0; mi < 4; ++mi)
#pragma unroll
                for (int ni = 0; ni < 4; ++ni)
                    mma16816(acc[mi][ni], a[mi], bf[ni >> 1][(ni & 1) * 2], bf[ni >> 1][(ni & 1) * 2 + 1]);
        }
    }

    // ---- epilogue: exp + store E + deterministic partial row sums ----
    const int r0 = qt + wm * 64 + (lane >> 2);
    const int c0 = kt + wn * 32 + (lane & 3) * 2;
    const int pc = blockIdx.x * 4 + wn;

#pragma unroll
    for (int mi = 0; mi < 4; ++mi) {
        float s0 = 0.f, s1 = 0.f;
        const int rr = r0 + mi * 16;
#pragma unroll
        for (int ni = 0; ni < 4; ++ni) {
            float e0 = __expf(acc[mi][ni][0] * SCALE);
            float e1 = __expf(acc[mi][ni][1] * SCALE);
            float e2 = __expf(acc[mi][ni][2] * SCALE);
            float e3 = __expf(acc[mi][ni][3] * SCALE);
            s0 += e0 + e1; s1 += e2 + e3;
            float2 lo2{e0, e1}, hi2{e2, e3};
            *reinterpret_cast<float2*>(E + ((size_t)b * LQ + rr)     * LK + c0 + ni * 8) = lo2;
            *reinterpret_cast<float2*>(E + ((size_t)b * LQ + rr + 8) * LK + c0 + ni * 8) = hi2;
        }
        s0 += __shfl_xor_sync(0xFFFFFFFFu, s0, 1);
        s0 += __shfl_xor_sync(0xFFFFFFFFu, s0, 2);
        s1 += __shfl_xor_sync(0xFFFFFFFFu, s1, 1);
        s1 += __shfl_xor_sync(0xFFFFFFFFu, s1, 2);
        if ((lane & 3) == 0) {
            g_psums[((size_t)b * LQ + rr)     * NPS + pc] = s0;
            g_psums[((size_t)b * LQ + rr + 8) * NPS + pc] = s1;
        }
    }
}

// ---------------------------------------------------------------------------
// Kernel 2: normalize P in place + R = P·V. Same mma structure; V loaded with
// ldmatrix.trans straight from [k][d]-major smem. K loop: 16 chunks of 128.
// ---------------------------------------------------------------------------
__global__ __launch_bounds__(256, 1) void pv_kernel(float* __restrict__ P,
                                                    const float* __restrict__ V,
                                                    float* __restrict__ R) {
    extern __shared__ char sm[];
    const uint32_t sb = smem_u32(sm);

    const int tid = threadIdx.x, lane = tid & 31, wid = tid >> 5;
    const int wm = wid >> 2, wn = wid & 3;
    const int qt = blockIdx.x * 128, b = blockIdx.y;

    // row inverse sums, fixed summation order (deterministic)
    float* inv = reinterpret_cast<float*>(sm + 4 * TILE_B);
    if (tid < 128) {
        const float* ps = &g_psums[((size_t)b * LQ + qt + tid) * NPS];
        float s = 0.f;
#pragma unroll
        for (int j = 0; j < NPS; ++j) s += ps[j];
        inv[tid] = 1.f / s;
    }
    __syncthreads();

    float* Pb = P + ((size_t)b * LQ + qt) * LK;
    const float* Vb = V + (size_t)b * LK * DIM;

    float acc[4][4][4];
#pragma unroll
    for (int mi = 0; mi < 4; ++mi)
#pragma unroll
        for (int ni = 0; ni < 4; ++ni)
#pragma unroll
            for (int c = 0; c < 4; ++c) acc[mi][ni][c] = 0.f;

    const uint32_t aoff  = (uint32_t)((lane & 15) * RSB + (lane >> 4) * 16);
    // trans-B: rows are k, cols are d
    const uint32_t boffT = (uint32_t)(((lane & 7) + ((lane >> 3) & 1) * 8) * RSB + (lane >> 4) * 16);
    const uint32_t aHi = sb + 0 * TILE_B + (uint32_t)(wm * 64) * RSB + aoff;
    const uint32_t aLo = sb + 1 * TILE_B + (uint32_t)(wm * 64) * RSB + aoff;
    const uint32_t bHi = sb + 2 * TILE_B + boffT + (uint32_t)(wn * 32) * 2;
    const uint32_t bLo = sb + 3 * TILE_B + boffT + (uint32_t)(wn * 32) * 2;

    for (int kc = 0; kc < 16; ++kc) {
        if (kc) __syncthreads();   // protect smem reuse against previous mma reads

        // P chunk: normalize, write back, split into smem.  V chunk: split into smem.
#pragma unroll
        for (int it = 0; it < 16; ++it) {
            int f = tid + it * 256;
            int row = f >> 5, col = (f & 31) * 4;
            int so = row * RSB + col * 2;

            float* paddr = Pb + (size_t)row * LK + kc * 128 + col;
            float4 v = *reinterpret_cast<const float4*>(paddr);
            float iv = inv[row];
            v.x *= iv; v.y *= iv; v.z *= iv; v.w *= iv;
            *reinterpret_cast<float4*>(paddr) = v;     // final normalized P
            uint2 hi, lo;
            split4(v, hi, lo);
            *reinterpret_cast<uint2*>(sm + 0 * TILE_B + so) = hi;
            *reinterpret_cast<uint2*>(sm + 1 * TILE_B + so) = lo;

            // V rows here are k-rows (natural [k][d] orientation)
            float4 w = *reinterpret_cast<const float4*>(Vb + (size_t)(kc * 128 + row) * DIM + col);
            split4(w, hi, lo);
            *reinterpret_cast<uint2*>(sm + 2 * TILE_B + so) = hi;
            *reinterpret_cast<uint2*>(sm + 3 * TILE_B + so) = lo;
        }
        __syncthreads();

#pragma unroll
        for (int pass = 0; pass < 3; ++pass) {
            const uint32_t ab = (pass == 2) ? aLo : aHi;
            const uint32_t bb = (pass == 1) ? bLo : bHi;
#pragma unroll
            for (int ks = 0; ks < 8; ++ks) {
                uint32_t a[4][4];
#pragma unroll
                for (int mi = 0; mi < 4; ++mi) ldsm4(a[mi], ab + (uint32_t)(mi * 16) * RSB + ks * 32);
                uint32_t bf[2][4];
#pragma unroll
                for (int np = 0; np < 2; ++np)
                    ldsm4t(bf[np], bb + (uint32_t)(ks * 16) * RSB + np * 32);
#pragma unroll
                for (int mi = 0; mi < 4; ++mi)
#pragma unroll
                    for (int ni = 0; ni < 4; ++ni)
                        mma16816(acc[mi][ni], a[mi], bf[ni >> 1][(ni & 1) * 2], bf[ni >> 1][(ni & 1) * 2 + 1]);
            }
        }
    }

    // ---- epilogue: store R (already normalized) ----
    const int r0 = qt + wm * 64 + (lane >> 2);
    const int c0 = wn * 32 + (lane & 3) * 2;
#pragma unroll
    for (int mi = 0; mi < 4; ++mi) {
        const int rr = r0 + mi * 16;
#pragma unroll
        for (int ni = 0; ni < 4; ++ni) {
            float2 lo2{acc[mi][ni][0], acc[mi][ni][1]};
            float2 hi2{acc[mi][ni][2], acc[mi][ni][3]};
            *reinterpret_cast<float2*>(R + ((size_t)b * LQ + rr)     * DIM + c0 + ni * 8) = lo2;
            *reinterpret_cast<float2*>(R + ((size_t)b * LQ + rr + 8) * DIM + c0 + ni * 8) = hi2;
        }
    }
}

// ---------------------------------------------------------------------------
// Launch: d_out = [ R | P ]
// ---------------------------------------------------------------------------
extern "C" void kernel_launch(void* const* d_in, const int* in_sizes, int n_in,
                              void* d_out, int out_size) {
    const float* Q = (const float*)d_in[0];
    const float* K = (const float*)d_in[1];
    const float* V = (const float*)d_in[2];
    float* R = (float*)d_out;
    float* P = (float*)d_out + (size_t)BATCH * LQ * DIM;

    cudaFuncSetAttribute(qk_exp_kernel, cudaFuncAttributeMaxDynamicSharedMemorySize, SM_QK);
    cudaFuncSetAttribute(pv_kernel,     cudaFuncAttributeMaxDynamicSharedMemorySize, SM_PV);

    {
        dim3 grid(LK / 128, LQ / 128, BATCH);
        qk_exp_kernel<<<grid, 256, SM_QK>>>(Q, K, P);
    }
    {
        dim3 grid(LQ / 128, BATCH);
        pv_kernel<<<grid, 256, SM_PV>>>(P, V, R);
    }
}

// round 4
// speedup vs baseline: 1.6258x; 1.1197x over previous
#include <cuda_runtime.h>
#include <cuda_bf16.h>
#include <cstdint>

// ---------------------------------------------------------------------------
// Problem dims
// ---------------------------------------------------------------------------
static constexpr int BATCH = 16;
static constexpr int LQ    = 2048;
static constexpr int LK    = 2048;
static constexpr int DIM   = 128;
static constexpr float SCALE = 0.08838834764831845f;             // 1/sqrt(128)
static constexpr float SCALE_LOG2E = 0.08838834764831845f * 1.4426950408889634f;

static constexpr int NPS = LK / 32;   // 64 partial sums per row

__device__ float g_psums[(size_t)BATCH * LQ * NPS];

// ---------------------------------------------------------------------------
// PTX helpers (plain sm_80-class: ldmatrix + mma.sync, ex2.approx)
// ---------------------------------------------------------------------------
__device__ __forceinline__ uint32_t smem_u32(const void* p) {
    uint32_t a;
    asm("{ .reg .u64 t; cvta.to.shared.u64 t, %1; cvt.u32.u64 %0, t; }" : "=r"(a) : "l"(p));
    return a;
}
__device__ __forceinline__ float ex2(float x) {
    float r; asm("ex2.approx.f32 %0, %1;" : "=f"(r) : "f"(x)); return r;
}
__device__ __forceinline__ void ldsm4(uint32_t (&r)[4], uint32_t addr) {
    asm volatile("ldmatrix.sync.aligned.m8n8.x4.shared.b16 {%0,%1,%2,%3}, [%4];"
                 : "=r"(r[0]), "=r"(r[1]), "=r"(r[2]), "=r"(r[3]) : "r"(addr));
}
__device__ __forceinline__ void ldsm4t(uint32_t (&r)[4], uint32_t addr) {
    asm volatile("ldmatrix.sync.aligned.m8n8.x4.trans.shared.b16 {%0,%1,%2,%3}, [%4];"
                 : "=r"(r[0]), "=r"(r[1]), "=r"(r[2]), "=r"(r[3]) : "r"(addr));
}
__device__ __forceinline__ void mma16816(float (&d)[4], const uint32_t (&a)[4],
                                         uint32_t b0, uint32_t b1) {
    asm volatile(
        "mma.sync.aligned.m16n8k16.row.col.f32.bf16.bf16.f32 "
        "{%0,%1,%2,%3},{%4,%5,%6,%7},{%8,%9},{%0,%1,%2,%3};"
        : "+f"(d[0]), "+f"(d[1]), "+f"(d[2]), "+f"(d[3])
        : "r"(a[0]), "r"(a[1]), "r"(a[2]), "r"(a[3]), "r"(b0), "r"(b1));
}
__device__ __forceinline__ void split4(float4 v, uint2& hi, uint2& lo) {
    __nv_bfloat16 h0 = __float2bfloat16_rn(v.x);
    __nv_bfloat16 h1 = __float2bfloat16_rn(v.y);
    __nv_bfloat16 h2 = __float2bfloat16_rn(v.z);
    __nv_bfloat16 h3 = __float2bfloat16_rn(v.w);
    __nv_bfloat16 l0 = __float2bfloat16_rn(v.x - __bfloat162float(h0));
    __nv_bfloat16 l1 = __float2bfloat16_rn(v.y - __bfloat162float(h1));
    __nv_bfloat16 l2 = __float2bfloat16_rn(v.z - __bfloat162float(h2));
    __nv_bfloat16 l3 = __float2bfloat16_rn(v.w - __bfloat162float(h3));
    __nv_bfloat162 a{h0, h1}, b{h2, h3}, c{l0, l1}, d{l2, l3};
    hi.x = *reinterpret_cast<uint32_t*>(&a); hi.y = *reinterpret_cast<uint32_t*>(&b);
    lo.x = *reinterpret_cast<uint32_t*>(&c); lo.y = *reinterpret_cast<uint32_t*>(&d);
}

// ---------------------------------------------------------------------------
// QK kernel: 64(q) x 128(k) tile, 8 warps (2m x 4n), warp tile 32x32.
// E = exp2(Qs·K^T) with Qs = Q * SCALE*log2e.  2 CTAs/SM.
// ---------------------------------------------------------------------------
static constexpr int QK_RSB = 272;                 // 128 halves + 8 pad, bytes
static constexpr int QK_QT  = 64  * QK_RSB;        // 17408 per Q tile
static constexpr int QK_KT  = 128 * QK_RSB;        // 34816 per K tile
static constexpr int QK_QH = 0, QK_QL = QK_QT, QK_KH = 2 * QK_QT, QK_KL = 2 * QK_QT + QK_KT;
static constexpr int SM_QK = 2 * QK_QT + 2 * QK_KT;   // 104448

__global__ __launch_bounds__(256, 2) void qk_exp_kernel(const float* __restrict__ Q,
                                                        const float* __restrict__ Km,
                                                        float* __restrict__ E) {
    extern __shared__ char sm[];
    const uint32_t sb = smem_u32(sm);

    const int tid = threadIdx.x, lane = tid & 31, wid = tid >> 5;
    const int wm = wid >> 2, wn = wid & 3;     // 2 x 4 warps
    const int b = blockIdx.z, qt = blockIdx.y * 64, kt = blockIdx.x * 128;

    const float* Qb = Q  + ((size_t)b * LQ + qt) * DIM;
    const float* Kb = Km + ((size_t)b * LK + kt) * DIM;

    // Q: 64x128, scaled by SCALE*log2e, split hi/lo
#pragma unroll
    for (int it = 0; it < 8; ++it) {
        int f = tid + it * 256;               // 0..2047 float4
        int row = f >> 5, col = (f & 31) * 4;
        float4 v = *reinterpret_cast<const float4*>(Qb + (size_t)row * DIM + col);
        v.x *= SCALE_LOG2E; v.y *= SCALE_LOG2E; v.z *= SCALE_LOG2E; v.w *= SCALE_LOG2E;
        uint2 hi, lo; split4(v, hi, lo);
        int so = row * QK_RSB + col * 2;
        *reinterpret_cast<uint2*>(sm + QK_QH + so) = hi;
        *reinterpret_cast<uint2*>(sm + QK_QL + so) = lo;
    }
    // K: 128x128
#pragma unroll
    for (int it = 0; it < 16; ++it) {
        int f = tid + it * 256;               // 0..4095 float4
        int row = f >> 5, col = (f & 31) * 4;
        uint2 hi, lo;
        split4(*reinterpret_cast<const float4*>(Kb + (size_t)row * DIM + col), hi, lo);
        int so = row * QK_RSB + col * 2;
        *reinterpret_cast<uint2*>(sm + QK_KH + so) = hi;
        *reinterpret_cast<uint2*>(sm + QK_KL + so) = lo;
    }
    __syncthreads();

    float acc[2][4][4];
#pragma unroll
    for (int mi = 0; mi < 2; ++mi)
#pragma unroll
        for (int ni = 0; ni < 4; ++ni)
#pragma unroll
            for (int c = 0; c < 4; ++c) acc[mi][ni][c] = 0.f;

    const uint32_t aoff = (uint32_t)((lane & 15) * QK_RSB + (lane >> 4) * 16);
    const uint32_t boff = (uint32_t)(((lane & 7) + (lane >> 4) * 8) * QK_RSB + ((lane >> 3) & 1) * 16);
    const uint32_t aHi = sb + QK_QH + (uint32_t)(wm * 32) * QK_RSB + aoff;
    const uint32_t aLo = sb + QK_QL + (uint32_t)(wm * 32) * QK_RSB + aoff;
    const uint32_t bHi = sb + QK_KH + (uint32_t)(wn * 32) * QK_RSB + boff;
    const uint32_t bLo = sb + QK_KL + (uint32_t)(wn * 32) * QK_RSB + boff;

#pragma unroll
    for (int pass = 0; pass < 3; ++pass) {
        const uint32_t ab = (pass == 2) ? aLo : aHi;
        const uint32_t bb = (pass == 1) ? bLo : bHi;
#pragma unroll
        for (int ks = 0; ks < 8; ++ks) {
            uint32_t a[2][4];
#pragma unroll
            for (int mi = 0; mi < 2; ++mi) ldsm4(a[mi], ab + (uint32_t)(mi * 16) * QK_RSB + ks * 32);
            uint32_t bf[2][4];
#pragma unroll
            for (int np = 0; np < 2; ++np) ldsm4(bf[np], bb + (uint32_t)(np * 16) * QK_RSB + ks * 32);
#pragma unroll
            for (int mi = 0; mi < 2; ++mi)
#pragma unroll
                for (int ni = 0; ni < 4; ++ni)
                    mma16816(acc[mi][ni], a[mi], bf[ni >> 1][(ni & 1) * 2], bf[ni >> 1][(ni & 1) * 2 + 1]);
        }
    }

    // epilogue: exp2 + store E + deterministic partial sums
    const int r0 = qt + wm * 32 + (lane >> 2);
    const int c0 = kt + wn * 32 + (lane & 3) * 2;
    const int pc = blockIdx.x * 4 + wn;

#pragma unroll
    for (int mi = 0; mi < 2; ++mi) {
        float s0 = 0.f, s1 = 0.f;
        const int rr = r0 + mi * 16;
#pragma unroll
        for (int ni = 0; ni < 4; ++ni) {
            float e0 = ex2(acc[mi][ni][0]);
            float e1 = ex2(acc[mi][ni][1]);
            float e2 = ex2(acc[mi][ni][2]);
            float e3 = ex2(acc[mi][ni][3]);
            s0 += e0 + e1; s1 += e2 + e3;
            float2 lo2{e0, e1}, hi2{e2, e3};
            *reinterpret_cast<float2*>(E + ((size_t)b * LQ + rr)     * LK + c0 + ni * 8) = lo2;
            *reinterpret_cast<float2*>(E + ((size_t)b * LQ + rr + 8) * LK + c0 + ni * 8) = hi2;
        }
        s0 += __shfl_xor_sync(0xFFFFFFFFu, s0, 1);
        s0 += __shfl_xor_sync(0xFFFFFFFFu, s0, 2);
        s1 += __shfl_xor_sync(0xFFFFFFFFu, s1, 1);
        s1 += __shfl_xor_sync(0xFFFFFFFFu, s1, 2);
        if ((lane & 3) == 0) {
            g_psums[((size_t)b * LQ + rr)     * NPS + pc] = s0;
            g_psums[((size_t)b * LQ + rr + 8) * NPS + pc] = s1;
        }
    }
}

// ---------------------------------------------------------------------------
// PV kernel: 64(q) x 128(d), K in 32 chunks of 64, double-buffered smem +
// register prefetch. Normalizes P in place. 2 CTAs/SM.
// ---------------------------------------------------------------------------
static constexpr int PV_ARS = 144;                 // A row: 64 halves + 8 pad
static constexpr int PV_BRS = 272;                 // B row: 128 halves + 8 pad
static constexpr int PV_AT  = 64 * PV_ARS;         // 9216
static constexpr int PV_BT  = 64 * PV_BRS;         // 17408
static constexpr int PV_AH = 0, PV_AL = PV_AT, PV_BH = 2 * PV_AT, PV_BL = 2 * PV_AT + PV_BT;
static constexpr int PV_STAGE = 2 * PV_AT + 2 * PV_BT;   // 53248
static constexpr int PV_INV = 2 * PV_STAGE;              // 106496
static constexpr int SM_PV  = PV_INV + 256;              // 106752

__global__ __launch_bounds__(256, 2) void pv_kernel(float* __restrict__ P,
                                                    const float* __restrict__ V,
                                                    float* __restrict__ R) {
    extern __shared__ char sm[];
    const uint32_t sb = smem_u32(sm);

    const int tid = threadIdx.x, lane = tid & 31, wid = tid >> 5;
    const int wm = wid >> 2, wn = wid & 3;
    const int qt = blockIdx.x * 64, b = blockIdx.y;

    float* inv = reinterpret_cast<float*>(sm + PV_INV);
    if (tid < 64) {
        const float* ps = &g_psums[((size_t)b * LQ + qt + tid) * NPS];
        float s = 0.f;
#pragma unroll
        for (int j = 0; j < NPS; ++j) s += ps[j];
        inv[tid] = 1.f / s;
    }
    __syncthreads();

    float* Pb = P + ((size_t)b * LQ + qt) * LK;
    const float* Vb = V + (size_t)b * LK * DIM;

    float acc[2][4][4];
#pragma unroll
    for (int mi = 0; mi < 2; ++mi)
#pragma unroll
        for (int ni = 0; ni < 4; ++ni)
#pragma unroll
            for (int c = 0; c < 4; ++c) acc[mi][ni][c] = 0.f;

    const uint32_t aoff  = (uint32_t)((lane & 15) * PV_ARS + (lane >> 4) * 16);
    const uint32_t boffT = (uint32_t)(((lane & 7) + ((lane >> 3) & 1) * 8) * PV_BRS + (lane >> 4) * 16);

    float4 pbuf[4], vbuf[8];
    // prologue: load chunk 0
#pragma unroll
    for (int it = 0; it < 4; ++it) {
        int idx = tid + it * 256, row = idx >> 4, col = (idx & 15) * 4;
        pbuf[it] = *reinterpret_cast<const float4*>(Pb + (size_t)row * LK + col);
    }
#pragma unroll
    for (int it = 0; it < 8; ++it) {
        int idx = tid + it * 256, row = idx >> 5, col = (idx & 31) * 4;
        vbuf[it] = *reinterpret_cast<const float4*>(Vb + (size_t)row * DIM + col);
    }

    for (int kc = 0; kc < 32; ++kc) {
        const int st = (kc & 1) * PV_STAGE;
        // convert current chunk (held in regs) -> smem; write normalized P
#pragma unroll
        for (int it = 0; it < 4; ++it) {
            int idx = tid + it * 256, row = idx >> 4, col = (idx & 15) * 4;
            float4 v = pbuf[it];
            float iv = inv[row];
            v.x *= iv; v.y *= iv; v.z *= iv; v.w *= iv;
            *reinterpret_cast<float4*>(Pb + (size_t)row * LK + kc * 64 + col) = v;
            uint2 hi, lo; split4(v, hi, lo);
            int so = st + row * PV_ARS + col * 2;
            *reinterpret_cast<uint2*>(sm + PV_AH + so) = hi;
            *reinterpret_cast<uint2*>(sm + PV_AL + so) = lo;
        }
#pragma unroll
        for (int it = 0; it < 8; ++it) {
            int idx = tid + it * 256, row = idx >> 5, col = (idx & 31) * 4;
            uint2 hi, lo; split4(vbuf[it], hi, lo);
            int so = st + row * PV_BRS + col * 2;
            *reinterpret_cast<uint2*>(sm + PV_BH + so) = hi;
            *reinterpret_cast<uint2*>(sm + PV_BL + so) = lo;
        }
        __syncthreads();

        // prefetch next chunk into regs (consumed next iteration, hidden by mma)
        if (kc < 31) {
#pragma unroll
            for (int it = 0; it < 4; ++it) {
                int idx = tid + it * 256, row = idx >> 4, col = (idx & 15) * 4;
                pbuf[it] = *reinterpret_cast<const float4*>(Pb + (size_t)row * LK + (kc + 1) * 64 + col);
            }
#pragma unroll
            for (int it = 0; it < 8; ++it) {
                int idx = tid + it * 256, row = idx >> 5, col = (idx & 31) * 4;
                vbuf[it] = *reinterpret_cast<const float4*>(Vb + (size_t)((kc + 1) * 64 + row) * DIM + col);
            }
        }

        const uint32_t aHi = sb + PV_AH + st + (uint32_t)(wm * 32) * PV_ARS + aoff;
        const uint32_t aLo = sb + PV_AL + st + (uint32_t)(wm * 32) * PV_ARS + aoff;
        const uint32_t bHi = sb + PV_BH + st + boffT + (uint32_t)(wn * 32) * 2;
        const uint32_t bLo = sb + PV_BL + st + boffT + (uint32_t)(wn * 32) * 2;

#pragma unroll
        for (int pass = 0; pass < 3; ++pass) {
            const uint32_t ab = (pass == 2) ? aLo : aHi;
            const uint32_t bb = (pass == 1) ? bLo : bHi;
#pragma unroll
            for (int ks = 0; ks < 4; ++ks) {
                uint32_t a[2][4];
#pragma unroll
                for (int mi = 0; mi < 2; ++mi) ldsm4(a[mi], ab + (uint32_t)(mi * 16) * PV_ARS + ks * 32);
                uint32_t bf[2][4];
#pragma unroll
                for (int np = 0; np < 2; ++np) ldsm4t(bf[np], bb + (uint32_t)(ks * 16) * PV_BRS + np * 32);
#pragma unroll
                for (int mi = 0; mi < 2; ++mi)
#pragma unroll
                    for (int ni = 0; ni < 4; ++ni)
                        mma16816(acc[mi][ni], a[mi], bf[ni >> 1][(ni & 1) * 2], bf[ni >> 1][(ni & 1) * 2 + 1]);
            }
        }
    }

    // epilogue: R (A was normalized P)
    const int r0 = qt + wm * 32 + (lane >> 2);
    const int c0 = wn * 32 + (lane & 3) * 2;
#pragma unroll
    for (int mi = 0; mi < 2; ++mi) {
        const int rr = r0 + mi * 16;
#pragma unroll
        for (int ni = 0; ni < 4; ++ni) {
            float2 lo2{acc[mi][ni][0], acc[mi][ni][1]};
            float2 hi2{acc[mi][ni][2], acc[mi][ni][3]};
            *reinterpret_cast<float2*>(R + ((size_t)b * LQ + rr)     * DIM + c0 + ni * 8) = lo2;
            *reinterpret_cast<float2*>(R + ((size_t)b * LQ + rr + 8) * DIM + c0 + ni * 8) = hi2;
        }
    }
}

// ---------------------------------------------------------------------------
// Launch: d_out = [ R | P ]
// ---------------------------------------------------------------------------
extern "C" void kernel_launch(void* const* d_in, const int* in_sizes, int n_in,
                              void* d_out, int out_size) {
    const float* Q = (const float*)d_in[0];
    const float* K = (const float*)d_in[1];
    const float* V = (const float*)d_in[2];
    float* R = (float*)d_out;
    float* P = (float*)d_out + (size_t)BATCH * LQ * DIM;

    cudaFuncSetAttribute(qk_exp_kernel, cudaFuncAttributeMaxDynamicSharedMemorySize, SM_QK);
    cudaFuncSetAttribute(pv_kernel,     cudaFuncAttributeMaxDynamicSharedMemorySize, SM_PV);

    {
        dim3 grid(LK / 128, LQ / 64, BATCH);
        qk_exp_kernel<<<grid, 256, SM_QK>>>(Q, K, P);
    }
    {
        dim3 grid(LQ / 64, BATCH);
        pv_kernel<<<grid, 256, SM_PV>>>(P, V, R);
    }
}